// round 1
// baseline (speedup 1.0000x reference)
#include <cuda_runtime.h>
#include <cuda_bf16.h>
#include <cstdint>

// Problem constants
#define B_    16
#define CI_   64
#define CO_   128
#define H_    128
#define W_    128
#define KH_   3
#define KW_   3
#define HO_   126
#define WO_   126
#define K_    576          // CI*KH*KW
#define L_    (HO_*WO_)    // 15876
#define YSIZE (B_*CO_*HO_*WO_)   // 32514048

// Scratch (allocation-free: __device__ globals)
__device__ float g_wnT[K_ * CO_];     // normalized weights, transposed [k][co]
__device__ int   g_winners[B_ * CO_]; // argmax index per (b, co)

// ---------------------------------------------------------------------------
// 1) Normalize weights per output channel; write transposed wnT[k][co]
// ---------------------------------------------------------------------------
__global__ void normalize_w_kernel(const float* __restrict__ w) {
    int co = blockIdx.x;
    int t  = threadIdx.x;
    __shared__ double red[256];
    double s = 0.0;
    for (int k = t; k < K_; k += 256) {
        float v = w[co * K_ + k];
        s += (double)v * (double)v;
    }
    red[t] = s;
    __syncthreads();
    for (int o = 128; o > 0; o >>= 1) {
        if (t < o) red[t] += red[t + o];
        __syncthreads();
    }
    double nrm = sqrt(red[0]);
    float inv = (nrm == 0.0) ? 1.0f : (float)(1.0 / nrm);
    for (int k = t; k < K_; k += 256) {
        g_wnT[k * CO_ + co] = w[co * K_ + k] * inv;
    }
}

// ---------------------------------------------------------------------------
// 2) Conv kernel: implicit GEMM, one block per (batch, output row).
//    Block tile: 128 co x 128 wo (126 valid), K chunks of 16 via smem.
//    Thread micro-tile: 8 co x 8 wo, packed as f32x2 (FFMA2).
// ---------------------------------------------------------------------------
#define FFMA2(d, a, b) \
    asm("fma.rn.f32x2 %0, %1, %2, %0;" : "+l"(d) : "l"(a), "l"(b))

__global__ __launch_bounds__(256, 2)
void conv_kernel(const float* __restrict__ x,
                 const float* __restrict__ bias,
                 float* __restrict__ y) {
    const int ho = blockIdx.x;        // 0..125
    const int b  = blockIdx.y;        // 0..15
    const int t  = threadIdx.x;
    const int tx = t & 15;            // wo group: covers wo in [tx*8, tx*8+8)
    const int ty = t >> 4;            // co group: covers co in [ty*8, ty*8+8)

    // A: duplicated-pair f32x2 per co value; B: plain floats (read as f32x2)
    __shared__ unsigned long long As2[16][CO_];   // 16 KB
    __shared__ float              Bs [16][128];   // 8 KB

    unsigned long long acc[8][4];
    #pragma unroll
    for (int i = 0; i < 8; i++)
        #pragma unroll
        for (int j = 0; j < 4; j++) acc[i][j] = 0ull;

    const float* xb = x + (size_t)b * CI_ * H_ * W_;

    for (int k0 = 0; k0 < K_; k0 += 16) {
        __syncthreads();
        // cooperative load: 2048 A elems + 2048 B elems, 8 each per thread
        #pragma unroll
        for (int i = 0; i < 8; i++) {
            int idx = i * 256 + t;
            int kk = idx >> 7;        // 0..15
            int c  = idx & 127;       // co for A, wo for B
            int kg = k0 + kk;
            // A: wnT[kg][c], duplicated into both f32x2 halves
            unsigned int bits = __float_as_uint(g_wnT[kg * CO_ + c]);
            As2[kk][c] = ((unsigned long long)bits << 32) | (unsigned long long)bits;
            // B: x[b, ci, ho+kh, kw+c]  (k = ci*9 + kh*3 + kw, channel-major)
            int ci = kg / 9;
            int r  = kg - ci * 9;
            int kh = r / 3;
            int kw = r - kh * 3;
            float bv = 0.0f;
            if (c < WO_)
                bv = xb[((size_t)ci * H_ + (ho + kh)) * W_ + (kw + c)];
            Bs[kk][c] = bv;
        }
        __syncthreads();

        #pragma unroll
        for (int kk = 0; kk < 16; kk++) {
            unsigned long long a2[8], b2[4];
            const ulonglong2* ap = reinterpret_cast<const ulonglong2*>(&As2[kk][ty * 8]);
            ulonglong2 A0 = ap[0], A1 = ap[1], A2v = ap[2], A3 = ap[3];
            a2[0] = A0.x;  a2[1] = A0.y;
            a2[2] = A1.x;  a2[3] = A1.y;
            a2[4] = A2v.x; a2[5] = A2v.y;
            a2[6] = A3.x;  a2[7] = A3.y;
            const ulonglong2* bp = reinterpret_cast<const ulonglong2*>(&Bs[kk][tx * 8]);
            ulonglong2 B0 = bp[0], B1 = bp[1];
            b2[0] = B0.x; b2[1] = B0.y; b2[2] = B1.x; b2[3] = B1.y;
            #pragma unroll
            for (int i = 0; i < 8; i++)
                #pragma unroll
                for (int j = 0; j < 4; j++)
                    FFMA2(acc[i][j], a2[i], b2[j]);
        }
    }

    // store: y[b, co, ho, wo] for valid wo
    #pragma unroll
    for (int i = 0; i < 8; i++) {
        int co = ty * 8 + i;
        float bs = bias[co];
        size_t base = (((size_t)b * CO_ + co) * HO_ + ho) * WO_;
        #pragma unroll
        for (int j = 0; j < 4; j++) {
            int wo = tx * 8 + 2 * j;
            unsigned long long v = acc[i][j];
            float lo = __uint_as_float((unsigned int)(v & 0xffffffffull));
            float hi = __uint_as_float((unsigned int)(v >> 32));
            if (wo < WO_)     y[base + wo]     = lo + bs;
            if (wo + 1 < WO_) y[base + wo + 1] = hi + bs;
        }
    }
}

// ---------------------------------------------------------------------------
// 3) Argmax over L per (b, co), first-index tie-break (jnp.argmax semantics)
// ---------------------------------------------------------------------------
__global__ void argmax_kernel(const float* __restrict__ y) {
    int bc = blockIdx.x;              // b*CO_ + co
    int t  = threadIdx.x;
    const float* p = y + (size_t)bc * L_;
    float best = -3.402823466e+38f;
    int   bi   = 0x7fffffff;
    for (int l = t; l < L_; l += 256) {
        float v = p[l];
        if (v > best) { best = v; bi = l; }   // per-thread indices ascending
    }
    __shared__ float sv[256];
    __shared__ int   si[256];
    sv[t] = best; si[t] = bi;
    __syncthreads();
    for (int o = 128; o > 0; o >>= 1) {
        if (t < o) {
            float v2 = sv[t + o]; int i2 = si[t + o];
            if (v2 > sv[t] || (v2 == sv[t] && i2 < si[t])) { sv[t] = v2; si[t] = i2; }
        }
        __syncthreads();
    }
    if (t == 0) g_winners[bc] = si[0];
}

// ---------------------------------------------------------------------------
// 4) delta_w[co][k] = mean over b of winning patch element
// ---------------------------------------------------------------------------
__global__ void delta_kernel(const float* __restrict__ x, float* __restrict__ dw) {
    int co = blockIdx.x;
    int k  = threadIdx.x;
    if (k >= K_) return;
    int ci = k / 9;
    int r  = k - ci * 9;
    int kh = r / 3;
    int kw = r - kh * 3;
    float s = 0.0f;
    #pragma unroll
    for (int b = 0; b < B_; b++) {
        int l  = g_winners[b * CO_ + co];
        int ho = l / WO_;
        int wo = l - ho * WO_;
        s += x[(((size_t)b * CI_ + ci) * H_ + (ho + kh)) * W_ + (wo + kw)];
    }
    dw[co * K_ + k] = s * (1.0f / (float)B_);
}

// ---------------------------------------------------------------------------
extern "C" void kernel_launch(void* const* d_in, const int* in_sizes, int n_in,
                              void* d_out, int out_size) {
    const float* x    = (const float*)d_in[0];   // (16,64,128,128)
    const float* w    = (const float*)d_in[1];   // (128,64,3,3)
    const float* bias = (const float*)d_in[2];   // (128,)
    float* out = (float*)d_out;
    float* y   = out;                 // (16,128,126,126)
    float* dw  = out + YSIZE;         // (128,64,3,3)

    normalize_w_kernel<<<CO_, 256>>>(w);
    dim3 cgrid(HO_, B_);
    conv_kernel<<<cgrid, 256>>>(x, bias, y);
    argmax_kernel<<<B_ * CO_, 256>>>(y);
    delta_kernel<<<CO_, 576>>>(x, dw);
}

// round 2
// speedup vs baseline: 1.0007x; 1.0007x over previous
#include <cuda_runtime.h>
#include <cuda_bf16.h>
#include <cstdint>

// Problem constants
#define B_    16
#define CI_   64
#define CO_   128
#define H_    128
#define W_    128
#define KH_   3
#define KW_   3
#define HO_   126
#define WO_   126
#define K_    576          // CI*KH*KW
#define L_    (HO_*WO_)    // 15876
#define YSIZE (B_*CO_*HO_*WO_)   // 32514048

// Scratch (allocation-free: __device__ globals)
__device__ float g_wnT[K_ * CO_];     // normalized weights, transposed [k][co]
__device__ int   g_winners[B_ * CO_]; // argmax index per (b, co)

// ---------------------------------------------------------------------------
// 1) Normalize weights per output channel; write transposed wnT[k][co]
// ---------------------------------------------------------------------------
__global__ void normalize_w_kernel(const float* __restrict__ w) {
    int co = blockIdx.x;
    int t  = threadIdx.x;
    __shared__ double red[256];
    double s = 0.0;
    for (int k = t; k < K_; k += 256) {
        float v = w[co * K_ + k];
        s += (double)v * (double)v;
    }
    red[t] = s;
    __syncthreads();
    for (int o = 128; o > 0; o >>= 1) {
        if (t < o) red[t] += red[t + o];
        __syncthreads();
    }
    double nrm = sqrt(red[0]);
    float inv = (nrm == 0.0) ? 1.0f : (float)(1.0 / nrm);
    for (int k = t; k < K_; k += 256) {
        g_wnT[k * CO_ + co] = w[co * K_ + k] * inv;
    }
}

// ---------------------------------------------------------------------------
// 2) Conv kernel: implicit GEMM, one block per (batch, output row).
//    Block tile: 128 co x 128 wo (126 valid), K chunks of 16 via smem.
//    Thread micro-tile: 8 co x 8 wo, packed as f32x2 (FFMA2).
// ---------------------------------------------------------------------------
#define FFMA2(d, a, b) \
    asm("fma.rn.f32x2 %0, %1, %2, %0;" : "+l"(d) : "l"(a), "l"(b))

__global__ __launch_bounds__(256, 2)
void conv_kernel(const float* __restrict__ x,
                 const float* __restrict__ bias,
                 float* __restrict__ y) {
    const int ho = blockIdx.x;        // 0..125
    const int b  = blockIdx.y;        // 0..15
    const int t  = threadIdx.x;
    const int tx = t & 15;            // wo group: covers wo in [tx*8, tx*8+8)
    const int ty = t >> 4;            // co group: covers co in [ty*8, ty*8+8)

    // A: duplicated-pair f32x2 per co value; B: plain floats (read as f32x2)
    __shared__ unsigned long long As2[16][CO_];   // 16 KB
    __shared__ float              Bs [16][128];   // 8 KB

    unsigned long long acc[8][4];
    #pragma unroll
    for (int i = 0; i < 8; i++)
        #pragma unroll
        for (int j = 0; j < 4; j++) acc[i][j] = 0ull;

    const float* xb = x + (size_t)b * CI_ * H_ * W_;

    for (int k0 = 0; k0 < K_; k0 += 16) {
        __syncthreads();
        // cooperative load: 2048 A elems + 2048 B elems, 8 each per thread
        #pragma unroll
        for (int i = 0; i < 8; i++) {
            int idx = i * 256 + t;
            int kk = idx >> 7;        // 0..15
            int c  = idx & 127;       // co for A, wo for B
            int kg = k0 + kk;
            // A: wnT[kg][c], duplicated into both f32x2 halves
            unsigned int bits = __float_as_uint(g_wnT[kg * CO_ + c]);
            As2[kk][c] = ((unsigned long long)bits << 32) | (unsigned long long)bits;
            // B: x[b, ci, ho+kh, kw+c]  (k = ci*9 + kh*3 + kw, channel-major)
            int ci = kg / 9;
            int r  = kg - ci * 9;
            int kh = r / 3;
            int kw = r - kh * 3;
            float bv = 0.0f;
            if (c < WO_)
                bv = xb[((size_t)ci * H_ + (ho + kh)) * W_ + (kw + c)];
            Bs[kk][c] = bv;
        }
        __syncthreads();

        #pragma unroll
        for (int kk = 0; kk < 16; kk++) {
            unsigned long long a2[8], b2[4];
            const ulonglong2* ap = reinterpret_cast<const ulonglong2*>(&As2[kk][ty * 8]);
            ulonglong2 A0 = ap[0], A1 = ap[1], A2v = ap[2], A3 = ap[3];
            a2[0] = A0.x;  a2[1] = A0.y;
            a2[2] = A1.x;  a2[3] = A1.y;
            a2[4] = A2v.x; a2[5] = A2v.y;
            a2[6] = A3.x;  a2[7] = A3.y;
            const ulonglong2* bp = reinterpret_cast<const ulonglong2*>(&Bs[kk][tx * 8]);
            ulonglong2 B0 = bp[0], B1 = bp[1];
            b2[0] = B0.x; b2[1] = B0.y; b2[2] = B1.x; b2[3] = B1.y;
            #pragma unroll
            for (int i = 0; i < 8; i++)
                #pragma unroll
                for (int j = 0; j < 4; j++)
                    FFMA2(acc[i][j], a2[i], b2[j]);
        }
    }

    // store: y[b, co, ho, wo] for valid wo
    #pragma unroll
    for (int i = 0; i < 8; i++) {
        int co = ty * 8 + i;
        float bs = bias[co];
        size_t base = (((size_t)b * CO_ + co) * HO_ + ho) * WO_;
        #pragma unroll
        for (int j = 0; j < 4; j++) {
            int wo = tx * 8 + 2 * j;
            unsigned long long v = acc[i][j];
            float lo = __uint_as_float((unsigned int)(v & 0xffffffffull));
            float hi = __uint_as_float((unsigned int)(v >> 32));
            if (wo < WO_)     y[base + wo]     = lo + bs;
            if (wo + 1 < WO_) y[base + wo + 1] = hi + bs;
        }
    }
}

// ---------------------------------------------------------------------------
// 3) Argmax over L per (b, co), first-index tie-break (jnp.argmax semantics)
// ---------------------------------------------------------------------------
__global__ void argmax_kernel(const float* __restrict__ y) {
    int bc = blockIdx.x;              // b*CO_ + co
    int t  = threadIdx.x;
    const float* p = y + (size_t)bc * L_;
    float best = -3.402823466e+38f;
    int   bi   = 0x7fffffff;
    for (int l = t; l < L_; l += 256) {
        float v = p[l];
        if (v > best) { best = v; bi = l; }   // per-thread indices ascending
    }
    __shared__ float sv[256];
    __shared__ int   si[256];
    sv[t] = best; si[t] = bi;
    __syncthreads();
    for (int o = 128; o > 0; o >>= 1) {
        if (t < o) {
            float v2 = sv[t + o]; int i2 = si[t + o];
            if (v2 > sv[t] || (v2 == sv[t] && i2 < si[t])) { sv[t] = v2; si[t] = i2; }
        }
        __syncthreads();
    }
    if (t == 0) g_winners[bc] = si[0];
}

// ---------------------------------------------------------------------------
// 4) delta_w[co][k] = mean over b of winning patch element
// ---------------------------------------------------------------------------
__global__ void delta_kernel(const float* __restrict__ x, float* __restrict__ dw) {
    int co = blockIdx.x;
    int k  = threadIdx.x;
    if (k >= K_) return;
    int ci = k / 9;
    int r  = k - ci * 9;
    int kh = r / 3;
    int kw = r - kh * 3;
    float s = 0.0f;
    #pragma unroll
    for (int b = 0; b < B_; b++) {
        int l  = g_winners[b * CO_ + co];
        int ho = l / WO_;
        int wo = l - ho * WO_;
        s += x[(((size_t)b * CI_ + ci) * H_ + (ho + kh)) * W_ + (wo + kw)];
    }
    dw[co * K_ + k] = s * (1.0f / (float)B_);
}

// ---------------------------------------------------------------------------
extern "C" void kernel_launch(void* const* d_in, const int* in_sizes, int n_in,
                              void* d_out, int out_size) {
    const float* x    = (const float*)d_in[0];   // (16,64,128,128)
    const float* w    = (const float*)d_in[1];   // (128,64,3,3)
    const float* bias = (const float*)d_in[2];   // (128,)
    float* out = (float*)d_out;
    float* y   = out;                 // (16,128,126,126)
    float* dw  = out + YSIZE;         // (128,64,3,3)

    normalize_w_kernel<<<CO_, 256>>>(w);
    dim3 cgrid(HO_, B_);
    conv_kernel<<<cgrid, 256>>>(x, bias, y);
    argmax_kernel<<<B_ * CO_, 256>>>(y);
    delta_kernel<<<CO_, 576>>>(x, dw);
}